// round 4
// baseline (speedup 1.0000x reference)
#include <cuda_runtime.h>
#include <math.h>
#include <stdint.h>

// Problem constants
#define BB 512
#define TT 168
#define II 64
#define HH 256
#define GG 1024   // 4*H
#define BT (BB*TT)
#define CL 8      // cluster size (gate-dimension split)
#define GST 132   // gates smem row stride (floats)

// ---------------------------------------------------------------------------
// Scratch (device globals: allocation-free rule)
// ---------------------------------------------------------------------------
__device__ float g_gx[(size_t)BT * GG];   // gate pre-activations, interleaved gate layout
__device__ float g_out1[(size_t)BT * HH]; // layer-1 hidden outputs
__device__ float g_WT[HH * GG];           // W_ih transposed+interleaved (GEMM B)
__device__ uint32_t g_WhhP[HH * GG];      // W_hh tf32, per-rank B-fragment layout (see prep)
__device__ float g_bias[GG];              // b_ih+b_hh, interleaved

// Interleaving: column n = j*4+q maps to raw gate row r = q*256 + j
// (q: 0=i, 1=f, 2=g, 3=o).

// ---------------------------------------------------------------------------
// tf32 helpers
// ---------------------------------------------------------------------------
__device__ __forceinline__ uint32_t f2tf32(float x) {
    uint32_t r;
    asm("cvt.rna.tf32.f32 %0, %1;" : "=r"(r) : "f"(x));
    return r;
}

__device__ __forceinline__ void mma_tf32(float* c, const uint32_t* a, uint32_t b0, uint32_t b1) {
    asm volatile(
        "mma.sync.aligned.m16n8k8.row.col.f32.tf32.tf32.f32 "
        "{%0,%1,%2,%3}, {%4,%5,%6,%7}, {%8,%9}, {%0,%1,%2,%3};"
        : "+f"(c[0]), "+f"(c[1]), "+f"(c[2]), "+f"(c[3])
        : "r"(a[0]), "r"(a[1]), "r"(a[2]), "r"(a[3]), "r"(b0), "r"(b1));
}

// ---------------------------------------------------------------------------
// Weight prep: transpose + gate-interleave + bias combine + scan W permute.
// Scan W layout (per cluster rank owning n-slice [rank*128, rank*128+128)):
//   g_WhhP[rank*32768 + ((kblk*8 + wgrp)*32 + lane)*4 + nbodd*2 + slot]
// so one LDS.128 per (kblk, warp) yields B-fragments for both of the warp's
// n8-blocks (nb = wgrp*2 + nbodd). lane=(nin<<2)|(kin&3), slot=kin>>2.
// ---------------------------------------------------------------------------
__global__ void prep_weights(const float* __restrict__ W_ih,
                             const float* __restrict__ W_hh,
                             const float* __restrict__ b_ih,
                             const float* __restrict__ b_hh,
                             int K)
{
    int idx = blockIdx.x * 256 + threadIdx.x;  // 0 .. 256*1024-1
    int n = idx & (GG - 1);
    int k = idx >> 10;
    int j = n >> 2;
    int q = n & 3;
    int r = q * HH + j;
    if (k < K) g_WT[k * GG + n] = W_ih[r * K + k];

    {
        float w = W_hh[r * HH + k];
        int rank = n >> 7;
        int nb   = (n >> 3) & 15;
        int nin  = n & 7;
        int kblk = k >> 3, kin = k & 7;
        int lane = (nin << 2) | (kin & 3);
        int slot = kin >> 2;
        int wgrp = nb >> 1, nbodd = nb & 1;
        size_t o = (size_t)rank * 32768 +
                   (size_t)(((kblk * 8 + wgrp) * 32 + lane) * 4 + nbodd * 2 + slot);
        g_WhhP[o] = f2tf32(w);
    }
    if (k == 0) g_bias[n] = b_ih[r] + b_hh[r];
}

// ---------------------------------------------------------------------------
// Feed-forward GEMM (tensor cores, tf32): unchanged from R3.
// ---------------------------------------------------------------------------
template <int K>
__global__ __launch_bounds__(256)
void gemm_gx_tf32(const float* __restrict__ X_in)
{
    const float* X = X_in ? X_in : (const float*)g_out1;
    constexpr int KT = K / 32;

    __shared__ uint32_t sA[2][4096];
    __shared__ uint32_t sB[2][2048];

    const int tid  = threadIdx.x;
    const int warp = tid >> 5;
    const int lane = tid & 31;
    const int m0 = blockIdx.x * 128;
    const int n0 = blockIdx.y * 64;
    const int wmb = (warp >> 1) * 2;
    const int wnb = (warp & 1) * 4;

    float acc[2][4][4];
#pragma unroll
    for (int i = 0; i < 2; i++)
#pragma unroll
        for (int j = 0; j < 4; j++)
#pragma unroll
            for (int q = 0; q < 4; q++) acc[i][j][q] = 0.f;

    float4 av[4];
    float4 bv[2];

    auto ldg_tile = [&](int kt) {
#pragma unroll
        for (int i = 0; i < 4; i++) {
            int v = tid + 256 * i;
            int row = v >> 3;
            int kc = (v & 7) * 4;
            av[i] = *(const float4*)(X + (size_t)(m0 + row) * K + kt * 32 + kc);
        }
#pragma unroll
        for (int i = 0; i < 2; i++) {
            int v = tid + 256 * i;
            int row = v >> 4;
            int nc = (v & 15) * 4;
            bv[i] = *(const float4*)(g_WT + (size_t)(kt * 32 + row) * GG + n0 + nc);
        }
    };

    auto sts_tile = [&](int buf) {
#pragma unroll
        for (int i = 0; i < 4; i++) {
            int v = tid + 256 * i;
            int row = v >> 3;
            int kc0 = (v & 7) * 4;
            int mblk = row >> 4, mr = row & 15;
            float f[4] = {av[i].x, av[i].y, av[i].z, av[i].w};
#pragma unroll
            for (int j = 0; j < 4; j++) {
                int kc = kc0 + j;
                int kblk = kc >> 3, kin = kc & 7;
                int t = ((mr & 7) << 2) | (kin & 3);
                int slot = ((kin >> 2) << 1) | (mr >> 3);
                sA[buf][(((kblk << 3) | mblk) << 7) + (t << 2) + slot] = f2tf32(f[j]);
            }
        }
#pragma unroll
        for (int i = 0; i < 2; i++) {
            int v = tid + 256 * i;
            int row = v >> 4;
            int nc0 = (v & 15) * 4;
            int kblk = row >> 3, kin = row & 7;
            float f[4] = {bv[i].x, bv[i].y, bv[i].z, bv[i].w};
#pragma unroll
            for (int j = 0; j < 4; j++) {
                int nc = nc0 + j;
                int nblk = nc >> 3, nin = nc & 7;
                int t = (nin << 2) | (kin & 3);
                int slot = kin >> 2;
                sB[buf][(((kblk << 3) | nblk) << 6) + (t << 1) + slot] = f2tf32(f[j]);
            }
        }
    };

    auto compute = [&](int buf) {
#pragma unroll
        for (int ks = 0; ks < 4; ks++) {
            uint32_t afr[2][4];
            uint32_t bfr[4][2];
#pragma unroll
            for (int mi = 0; mi < 2; mi++) {
                uint4 a = *(const uint4*)&sA[buf][(((ks << 3) | (wmb + mi)) << 7) + (lane << 2)];
                afr[mi][0] = a.x; afr[mi][1] = a.y; afr[mi][2] = a.z; afr[mi][3] = a.w;
            }
#pragma unroll
            for (int ni = 0; ni < 4; ni++) {
                uint2 b = *(const uint2*)&sB[buf][(((ks << 3) | (wnb + ni)) << 6) + (lane << 1)];
                bfr[ni][0] = b.x; bfr[ni][1] = b.y;
            }
#pragma unroll
            for (int mi = 0; mi < 2; mi++)
#pragma unroll
                for (int ni = 0; ni < 4; ni++)
                    mma_tf32(acc[mi][ni], afr[mi], bfr[ni][0], bfr[ni][1]);
        }
    };

    ldg_tile(0);
    sts_tile(0);
    __syncthreads();
#pragma unroll
    for (int kt = 0; kt < KT; kt++) {
        if (kt + 1 < KT) ldg_tile(kt + 1);
        compute(kt & 1);
        if (kt + 1 < KT) sts_tile((kt + 1) & 1);
        __syncthreads();
    }

    const int g = lane >> 2;
    const int cq = lane & 3;
#pragma unroll
    for (int ni = 0; ni < 4; ni++) {
        int gn = n0 + ((wnb + ni) << 3) + cq * 2;
        float bx = g_bias[gn];
        float by = g_bias[gn + 1];
#pragma unroll
        for (int mi = 0; mi < 2; mi++) {
            int gm = m0 + ((wmb + mi) << 4) + g;
            float2 r0 = make_float2(acc[mi][ni][0] + bx, acc[mi][ni][1] + by);
            float2 r1 = make_float2(acc[mi][ni][2] + bx, acc[mi][ni][3] + by);
            *(float2*)(g_gx + (size_t)gm * GG + gn) = r0;
            *(float2*)(g_gx + (size_t)(gm + 8) * GG + gn) = r1;
        }
    }
}

// ---------------------------------------------------------------------------
// Cluster-distributed recurrent scan.
// Cluster of 8 CTAs owns 32 batch rows; CTA rank r owns gate cols
// [r*128, r*128+128) == h columns [r*32, r*32+32). W slice (128KB tf32,
// B-fragment order) is SMEM-RESIDENT — zero W traffic per step.
// Per step: each CTA computes gates[32 x 128] = gx + h[32,256] @ Wslice via
// m16n8k8 tf32 mma (A = h from local shA, full k=256), does the elementwise
// update for its 32 h columns, and pushes the new h values into every
// cluster CTA's shA (A-fragment slots) via st.shared::cluster.
// Sync: barrier.cluster pair after mma (reads done) and after update
// (writes released).
// ---------------------------------------------------------------------------
__global__ __launch_bounds__(256, 1) __cluster_dims__(CL, 1, 1)
void lstm_scan_cluster(float* __restrict__ out_in)
{
    float* out = out_in ? out_in : (float*)g_out1;

    extern __shared__ uint32_t smem_u[];
    uint32_t* sW  = smem_u;              // [32768] W slice, B-frag packed
    uint32_t* shA = smem_u + 32768;      // [8192] h, A-frag: [kblk32][mblk2][lane32][slot4]
    float* gates  = (float*)(smem_u + 32768 + 8192);  // [32][GST]

    const int tid  = threadIdx.x;
    const int warp = tid >> 5;
    const int lane = tid & 31;
    const int g    = lane >> 2;
    const int cq   = lane & 3;

    uint32_t rank;
    asm("mov.u32 %0, %%cluster_ctarank;" : "=r"(rank));
    const int cid = blockIdx.x >> 3;     // cluster id (x-major rank order)
    const int b0  = cid * 32;

    // ---- load resident W slice, zero shA ----
    {
        const uint4* Wg = ((const uint4*)g_WhhP) + (size_t)rank * 8192;
        uint4* sW4 = (uint4*)sW;
        for (int i = tid; i < 8192; i += 256) sW4[i] = Wg[i];
        for (int i = tid; i < 8192; i += 256) shA[i] = 0u;
    }

    // ---- peer shA base addresses (dsmem) ----
    uint32_t shA_local;
    asm("{ .reg .u64 t; cvta.to.shared.u64 t, %1; cvt.u32.u64 %0, t; }"
        : "=r"(shA_local) : "l"((void*)shA));
    uint32_t peerA[CL];
#pragma unroll
    for (int d = 0; d < CL; d++)
        asm("mapa.shared::cluster.u32 %0, %1, %2;" : "=r"(peerA[d]) : "r"(shA_local), "r"(d));

    // ---- update-thread constants ----
    const int jl   = tid & 31;           // local h column
    const int mgrp = tid >> 5;
    const int jg   = (int)rank * 32 + jl;
    const int kblkU = jg >> 3, kinU = jg & 7;
    const int laneBase = kinU & 3;
    const int slotBase = (kinU >> 2) << 1;

    float cst[4] = {0.f, 0.f, 0.f, 0.f};

    // gx row base pointers for this thread's mma fragments
    const size_t colbase = (size_t)rank * 128 + (size_t)(warp * 2) * 8 + cq * 2;

    asm volatile("barrier.cluster.arrive.aligned;" ::: "memory");
    asm volatile("barrier.cluster.wait.aligned;" ::: "memory");

    for (int t = 0; t < TT; t++) {
        // ---- gx fragment loads (deferred add; latency hidden by mma loop) ----
        float2 gv[2][2][2];   // [mi][ni][lo/hi row]
#pragma unroll
        for (int mi = 0; mi < 2; mi++)
#pragma unroll
            for (int ni = 0; ni < 2; ni++) {
                size_t col = colbase + ni * 8;
                int row = b0 + mi * 16 + g;
                gv[mi][ni][0] = *(const float2*)(g_gx + ((size_t)row * TT + t) * GG + col);
                gv[mi][ni][1] = *(const float2*)(g_gx + ((size_t)(row + 8) * TT + t) * GG + col);
            }

        // ---- mma: gates_acc = h @ Wslice (k = 256, 32 kblks) ----
        float acc[2][2][4];
#pragma unroll
        for (int mi = 0; mi < 2; mi++)
#pragma unroll
            for (int ni = 0; ni < 2; ni++)
#pragma unroll
                for (int q = 0; q < 4; q++) acc[mi][ni][q] = 0.f;

#pragma unroll 8
        for (int kb = 0; kb < 32; kb++) {
            uint4 a0v = *(const uint4*)&shA[((kb * 2 + 0) * 32 + lane) * 4];
            uint4 a1v = *(const uint4*)&shA[((kb * 2 + 1) * 32 + lane) * 4];
            uint4 bb  = *(const uint4*)&sW[((kb * 8 + warp) * 32 + lane) * 4];
            uint32_t a0[4] = {a0v.x, a0v.y, a0v.z, a0v.w};
            uint32_t a1[4] = {a1v.x, a1v.y, a1v.z, a1v.w};
            mma_tf32(acc[0][0], a0, bb.x, bb.y);
            mma_tf32(acc[0][1], a0, bb.z, bb.w);
            mma_tf32(acc[1][0], a1, bb.x, bb.y);
            mma_tf32(acc[1][1], a1, bb.z, bb.w);
        }

        // ---- gates = acc + gx -> smem ----
#pragma unroll
        for (int mi = 0; mi < 2; mi++)
#pragma unroll
            for (int ni = 0; ni < 2; ni++) {
                int nl = (warp * 2 + ni) * 8 + cq * 2;
                int m  = mi * 16 + g;
                *(float2*)(gates + m * GST + nl) =
                    make_float2(acc[mi][ni][0] + gv[mi][ni][0].x,
                                acc[mi][ni][1] + gv[mi][ni][0].y);
                *(float2*)(gates + (m + 8) * GST + nl) =
                    make_float2(acc[mi][ni][2] + gv[mi][ni][1].x,
                                acc[mi][ni][3] + gv[mi][ni][1].y);
            }

        // shA reads complete cluster-wide; gates visible locally
        asm volatile("barrier.cluster.arrive.aligned;" ::: "memory");
        asm volatile("barrier.cluster.wait.aligned;" ::: "memory");

        // ---- elementwise update for 4 rows, 1 h column ----
        float hval[4];
#pragma unroll
        for (int i = 0; i < 4; i++) {
            int m = mgrp * 4 + i;
            float4 gvv = *(const float4*)(gates + m * GST + jl * 4);
            float ig = 1.f / (1.f + __expf(-gvv.x));
            float fg = 1.f / (1.f + __expf(-gvv.y));
            float gg = tanhf(gvv.z);
            float og = 1.f / (1.f + __expf(-gvv.w));
            float cn = fg * cst[i] + ig * gg;
            cst[i] = cn;
            float h = og * tanhf(cn);
            hval[i] = h;
            uint32_t hb = f2tf32(h);
            int mr = m & 15, mblk = m >> 4;
            int laneA = ((mr & 7) << 2) | laneBase;
            int slot  = slotBase | (mr >> 3);
            uint32_t off = (uint32_t)((((kblkU * 2 + mblk) * 32 + laneA) * 4 + slot) * 4);
#pragma unroll
            for (int d = 0; d < CL; d++)
                asm volatile("st.shared::cluster.u32 [%0], %1;"
                             :: "r"(peerA[d] + off), "r"(hb) : "memory");
        }

        // release h writes; overlap gmem out stores with peers' arrival
        asm volatile("barrier.cluster.arrive.aligned;" ::: "memory");
#pragma unroll
        for (int i = 0; i < 4; i++) {
            int m = mgrp * 4 + i;
            out[((size_t)(b0 + m) * TT + t) * HH + jg] = hval[i];
        }
        asm volatile("barrier.cluster.wait.aligned;" ::: "memory");
    }
}

// ---------------------------------------------------------------------------
// Launch
// ---------------------------------------------------------------------------
extern "C" void kernel_launch(void* const* d_in, const int* in_sizes, int n_in,
                              void* d_out, int out_size)
{
    const float* x     = (const float*)d_in[0];
    const float* W_ih1 = (const float*)d_in[1];
    const float* W_hh1 = (const float*)d_in[2];
    const float* b_ih1 = (const float*)d_in[3];
    const float* b_hh1 = (const float*)d_in[4];
    const float* W_ih2 = (const float*)d_in[5];
    const float* W_hh2 = (const float*)d_in[6];
    const float* b_ih2 = (const float*)d_in[7];
    const float* b_hh2 = (const float*)d_in[8];
    float* out = (float*)d_out;

    const int scan_smem = 32768 * 4 + 8192 * 4 + 32 * GST * 4;  // 180,736 B
    static int attr_set = 0;
    cudaFuncSetAttribute(lstm_scan_cluster,
                         cudaFuncAttributeMaxDynamicSharedMemorySize, scan_smem);
    (void)attr_set;

    dim3 ggrid(BT / 128, GG / 64);  // 672 x 16

    // Layer 1
    prep_weights<<<1024, 256>>>(W_ih1, W_hh1, b_ih1, b_hh1, II);
    gemm_gx_tf32<II><<<ggrid, 256>>>(x);
    lstm_scan_cluster<<<BB / 32 * CL, 256, scan_smem>>>(nullptr);    // 128 CTAs

    // Layer 2
    prep_weights<<<1024, 256>>>(W_ih2, W_hh2, b_ih2, b_hh2, HH);
    gemm_gx_tf32<HH><<<ggrid, 256>>>(nullptr);
    lstm_scan_cluster<<<BB / 32 * CL, 256, scan_smem>>>(out);
}

// round 5
// speedup vs baseline: 1.1094x; 1.1094x over previous
#include <cuda_runtime.h>
#include <math.h>
#include <stdint.h>

// Problem constants
#define BB 512
#define TT 168
#define II 64
#define HH 256
#define GG 1024   // 4*H
#define BT (BB*TT)
#define GST 1032  // gates smem row stride (floats)

// ---------------------------------------------------------------------------
// Scratch (device globals: allocation-free rule)
// ---------------------------------------------------------------------------
__device__ float g_gx[(size_t)BT * GG];   // gate pre-activations, interleaved gate layout
__device__ float g_out1[(size_t)BT * HH]; // layer-1 hidden outputs
__device__ float g_WT[HH * GG];           // W_ih transposed+interleaved (GEMM B)
__device__ uint32_t g_WhhP[HH * GG];      // W_hh tf32, scan B-fragment layout (see prep)
__device__ float g_bias[GG];              // b_ih+b_hh, interleaved

// Interleaving: column n = j*4+q maps to raw gate row r = q*256 + j
// (q: 0=i, 1=f, 2=g, 3=o).

// ---------------------------------------------------------------------------
// tf32 helpers
// ---------------------------------------------------------------------------
__device__ __forceinline__ uint32_t f2tf32(float x) {
    uint32_t r;
    asm("cvt.rna.tf32.f32 %0, %1;" : "=r"(r) : "f"(x));
    return r;
}

__device__ __forceinline__ void mma_tf32(float* c, const uint32_t* a, uint32_t b0, uint32_t b1) {
    asm volatile(
        "mma.sync.aligned.m16n8k8.row.col.f32.tf32.tf32.f32 "
        "{%0,%1,%2,%3}, {%4,%5,%6,%7}, {%8,%9}, {%0,%1,%2,%3};"
        : "+f"(c[0]), "+f"(c[1]), "+f"(c[2]), "+f"(c[3])
        : "r"(a[0]), "r"(a[1]), "r"(a[2]), "r"(a[3]), "r"(b0), "r"(b1));
}

// ---------------------------------------------------------------------------
// Weight prep: transpose + gate-interleave + bias combine + scan W permute.
// Scan W layout: warp w (of 16) owns n8-blocks nb in [w*8, w*8+8).
// One uint4 packs B-fragments (uint2 each) of two adjacent nb (pair p):
//   g_WhhP[ (((kblk*16 + w)*4 + p)*32 + lane)*4 + odd*2 + slot ]
// lane=(nin<<2)|(kin&3), slot=kin>>2, nb = w*8 + p*2 + odd.
// One warp LDG.128 = 512B contiguous = fragments of 2 nb for one kblk.
// ---------------------------------------------------------------------------
__global__ void prep_weights(const float* __restrict__ W_ih,
                             const float* __restrict__ W_hh,
                             const float* __restrict__ b_ih,
                             const float* __restrict__ b_hh,
                             int K)
{
    int idx = blockIdx.x * 256 + threadIdx.x;  // 0 .. 256*1024-1
    int n = idx & (GG - 1);
    int k = idx >> 10;
    int j = n >> 2;
    int q = n & 3;
    int r = q * HH + j;
    if (k < K) g_WT[k * GG + n] = W_ih[r * K + k];

    {
        float wv = W_hh[r * HH + k];
        int nb = n >> 3, nin = n & 7;
        int w = nb >> 3, win = nb & 7, p = win >> 1, odd = win & 1;
        int kblk = k >> 3, kin = k & 7;
        int lane = (nin << 2) | (kin & 3);
        int slot = kin >> 2;
        size_t o = ((((size_t)(kblk * 16 + w) * 4 + p) * 32 + lane) << 2) + (odd << 1) + slot;
        g_WhhP[o] = f2tf32(wv);
    }
    if (k == 0) g_bias[n] = b_ih[r] + b_hh[r];
}

// ---------------------------------------------------------------------------
// Feed-forward GEMM (tensor cores, tf32): unchanged (validated R2-R4).
// ---------------------------------------------------------------------------
template <int K>
__global__ __launch_bounds__(256)
void gemm_gx_tf32(const float* __restrict__ X_in)
{
    const float* X = X_in ? X_in : (const float*)g_out1;
    constexpr int KT = K / 32;

    __shared__ uint32_t sA[2][4096];
    __shared__ uint32_t sB[2][2048];

    const int tid  = threadIdx.x;
    const int warp = tid >> 5;
    const int lane = tid & 31;
    const int m0 = blockIdx.x * 128;
    const int n0 = blockIdx.y * 64;
    const int wmb = (warp >> 1) * 2;
    const int wnb = (warp & 1) * 4;

    float acc[2][4][4];
#pragma unroll
    for (int i = 0; i < 2; i++)
#pragma unroll
        for (int j = 0; j < 4; j++)
#pragma unroll
            for (int q = 0; q < 4; q++) acc[i][j][q] = 0.f;

    float4 av[4];
    float4 bv[2];

    auto ldg_tile = [&](int kt) {
#pragma unroll
        for (int i = 0; i < 4; i++) {
            int v = tid + 256 * i;
            int row = v >> 3;
            int kc = (v & 7) * 4;
            av[i] = *(const float4*)(X + (size_t)(m0 + row) * K + kt * 32 + kc);
        }
#pragma unroll
        for (int i = 0; i < 2; i++) {
            int v = tid + 256 * i;
            int row = v >> 4;
            int nc = (v & 15) * 4;
            bv[i] = *(const float4*)(g_WT + (size_t)(kt * 32 + row) * GG + n0 + nc);
        }
    };

    auto sts_tile = [&](int buf) {
#pragma unroll
        for (int i = 0; i < 4; i++) {
            int v = tid + 256 * i;
            int row = v >> 3;
            int kc0 = (v & 7) * 4;
            int mblk = row >> 4, mr = row & 15;
            float f[4] = {av[i].x, av[i].y, av[i].z, av[i].w};
#pragma unroll
            for (int j = 0; j < 4; j++) {
                int kc = kc0 + j;
                int kblk = kc >> 3, kin = kc & 7;
                int t = ((mr & 7) << 2) | (kin & 3);
                int slot = ((kin >> 2) << 1) | (mr >> 3);
                sA[buf][(((kblk << 3) | mblk) << 7) + (t << 2) + slot] = f2tf32(f[j]);
            }
        }
#pragma unroll
        for (int i = 0; i < 2; i++) {
            int v = tid + 256 * i;
            int row = v >> 4;
            int nc0 = (v & 15) * 4;
            int kblk = row >> 3, kin = row & 7;
            float f[4] = {bv[i].x, bv[i].y, bv[i].z, bv[i].w};
#pragma unroll
            for (int j = 0; j < 4; j++) {
                int nc = nc0 + j;
                int nblk = nc >> 3, nin = nc & 7;
                int t = (nin << 2) | (kin & 3);
                int slot = kin >> 2;
                sB[buf][(((kblk << 3) | nblk) << 6) + (t << 1) + slot] = f2tf32(f[j]);
            }
        }
    };

    auto compute = [&](int buf) {
#pragma unroll
        for (int ks = 0; ks < 4; ks++) {
            uint32_t afr[2][4];
            uint32_t bfr[4][2];
#pragma unroll
            for (int mi = 0; mi < 2; mi++) {
                uint4 a = *(const uint4*)&sA[buf][(((ks << 3) | (wmb + mi)) << 7) + (lane << 2)];
                afr[mi][0] = a.x; afr[mi][1] = a.y; afr[mi][2] = a.z; afr[mi][3] = a.w;
            }
#pragma unroll
            for (int ni = 0; ni < 4; ni++) {
                uint2 b = *(const uint2*)&sB[buf][(((ks << 3) | (wnb + ni)) << 6) + (lane << 1)];
                bfr[ni][0] = b.x; bfr[ni][1] = b.y;
            }
#pragma unroll
            for (int mi = 0; mi < 2; mi++)
#pragma unroll
                for (int ni = 0; ni < 4; ni++)
                    mma_tf32(acc[mi][ni], afr[mi], bfr[ni][0], bfr[ni][1]);
        }
    };

    ldg_tile(0);
    sts_tile(0);
    __syncthreads();
#pragma unroll
    for (int kt = 0; kt < KT; kt++) {
        if (kt + 1 < KT) ldg_tile(kt + 1);
        compute(kt & 1);
        if (kt + 1 < KT) sts_tile((kt + 1) & 1);
        __syncthreads();
    }

    const int g = lane >> 2;
    const int cq = lane & 3;
#pragma unroll
    for (int ni = 0; ni < 4; ni++) {
        int gn = n0 + ((wnb + ni) << 3) + cq * 2;
        float bx = g_bias[gn];
        float by = g_bias[gn + 1];
#pragma unroll
        for (int mi = 0; mi < 2; mi++) {
            int gm = m0 + ((wmb + mi) << 4) + g;
            float2 r0 = make_float2(acc[mi][ni][0] + bx, acc[mi][ni][1] + by);
            float2 r1 = make_float2(acc[mi][ni][2] + bx, acc[mi][ni][3] + by);
            *(float2*)(g_gx + (size_t)gm * GG + gn) = r0;
            *(float2*)(g_gx + (size_t)(gm + 8) * GG + gn) = r1;
        }
    }
}

// ---------------------------------------------------------------------------
// Recurrent scan v2 (tensor cores, high-ILP streaming).
// 32 CTAs, MB=16 batch rows each, 512 threads (16 warps, 4/SMSP).
// Warp w owns gate n8-blocks [w*8, w*8+8) (64 gate cols).
// Per step:
//   acc  = gx fragments (LDG.64 direct into accumulators)
//   acc += h[16,256] @ W  (32 kblks; W reg-double-buffered LDG.128 stream,
//                          h A-fragments from 16KB shA via 1 LDS.128/kblk)
//   gates -> smem, sync, elementwise update (thread = 1 col x 8 rows),
//   h -> shA (tf32 A-frag) + out gmem, sync.
// ---------------------------------------------------------------------------
__global__ __launch_bounds__(512, 1)
void lstm_scan2(float* __restrict__ out_in)
{
    float* out = out_in ? out_in : (float*)g_out1;

    extern __shared__ uint32_t smem_u[];
    uint32_t* shA = smem_u;                     // [32 kblk][32 lane][4 slot]
    float* gates  = (float*)(smem_u + 4096);    // [16][GST]

    const int tid  = threadIdx.x;
    const int w    = tid >> 5;
    const int lane = tid & 31;
    const int g    = lane >> 2;
    const int cq   = lane & 3;
    const int b0   = blockIdx.x * 16;

    // update-phase constants: thread owns h column j, rows [rg*8, rg*8+8)
    const int j  = tid & 255;
    const int rg = tid >> 8;
    const int kblkU = j >> 3, kinU = j & 7;
    const int laneBase = kinU & 3;
    const int slotBase = (kinU >> 2) << 1;

    for (int i = tid; i < 4096; i += 512) shA[i] = 0u;
    float cst[8];
#pragma unroll
    for (int i = 0; i < 8; i++) cst[i] = 0.f;
    __syncthreads();

    const uint4* __restrict__ Wp = (const uint4*)g_WhhP;

    for (int t = 0; t < TT; t++) {
        // ---- acc = gx fragments (issue all 16 LDG.64 up front) ----
        float acc[8][4];
        {
            const float* rowlo = g_gx + ((size_t)(b0 + g) * TT + t) * GG + w * 64 + cq * 2;
            const float* rowhi = rowlo + (size_t)8 * TT * GG;
#pragma unroll
            for (int ni = 0; ni < 8; ni++) {
                float2 lo = *(const float2*)(rowlo + ni * 8);
                float2 hi = *(const float2*)(rowhi + ni * 8);
                acc[ni][0] = lo.x; acc[ni][1] = lo.y;
                acc[ni][2] = hi.x; acc[ni][3] = hi.y;
            }
        }

        // ---- mma over 32 kblks, W register double-buffered ----
        uint4 wb[2][4];
#pragma unroll
        for (int p = 0; p < 4; p++)
            wb[0][p] = Wp[(size_t)(((0 * 16 + w) * 4 + p) * 32) + lane];

#pragma unroll 4
        for (int kb = 0; kb < 32; kb++) {
            const int cur = kb & 1;
            const int nxt = cur ^ 1;
            if (kb < 31) {
#pragma unroll
                for (int p = 0; p < 4; p++)
                    wb[nxt][p] = Wp[(size_t)((((kb + 1) * 16 + w) * 4 + p) * 32) + lane];
            }
            uint4 av = *(const uint4*)&shA[(kb * 32 + lane) * 4];
            uint32_t a[4] = {av.x, av.y, av.z, av.w};
#pragma unroll
            for (int p = 0; p < 4; p++) {
                mma_tf32(acc[2 * p],     a, wb[cur][p].x, wb[cur][p].y);
                mma_tf32(acc[2 * p + 1], a, wb[cur][p].z, wb[cur][p].w);
            }
        }

        // ---- gates -> smem ----
#pragma unroll
        for (int ni = 0; ni < 8; ni++) {
            int n = w * 64 + ni * 8 + cq * 2;
            *(float2*)(gates + g * GST + n) = make_float2(acc[ni][0], acc[ni][1]);
            *(float2*)(gates + (g + 8) * GST + n) = make_float2(acc[ni][2], acc[ni][3]);
        }
        __syncthreads();

        // ---- elementwise LSTM update ----
#pragma unroll
        for (int i = 0; i < 8; i++) {
            int m = rg * 8 + i;
            float4 gv = *(const float4*)(gates + m * GST + j * 4);
            float ig = 1.f / (1.f + __expf(-gv.x));
            float fg = 1.f / (1.f + __expf(-gv.y));
            float gg = tanhf(gv.z);
            float og = 1.f / (1.f + __expf(-gv.w));
            float cn = fg * cst[i] + ig * gg;
            cst[i] = cn;
            float h = og * tanhf(cn);
            out[((size_t)(b0 + m) * TT + t) * HH + j] = h;
            int laneA = ((m & 7) << 2) | laneBase;
            int slot  = slotBase | (m >> 3);
            shA[(kblkU * 32 + laneA) * 4 + slot] = f2tf32(h);
        }
        __syncthreads();
    }
}

// ---------------------------------------------------------------------------
// Launch
// ---------------------------------------------------------------------------
extern "C" void kernel_launch(void* const* d_in, const int* in_sizes, int n_in,
                              void* d_out, int out_size)
{
    const float* x     = (const float*)d_in[0];
    const float* W_ih1 = (const float*)d_in[1];
    const float* W_hh1 = (const float*)d_in[2];
    const float* b_ih1 = (const float*)d_in[3];
    const float* b_hh1 = (const float*)d_in[4];
    const float* W_ih2 = (const float*)d_in[5];
    const float* W_hh2 = (const float*)d_in[6];
    const float* b_ih2 = (const float*)d_in[7];
    const float* b_hh2 = (const float*)d_in[8];
    float* out = (float*)d_out;

    const int scan_smem = 4096 * 4 + 16 * GST * 4;   // 82,432 B
    cudaFuncSetAttribute(lstm_scan2,
                         cudaFuncAttributeMaxDynamicSharedMemorySize, scan_smem);

    dim3 ggrid(BT / 128, GG / 64);  // 672 x 16

    // Layer 1
    prep_weights<<<1024, 256>>>(W_ih1, W_hh1, b_ih1, b_hh1, II);
    gemm_gx_tf32<II><<<ggrid, 256>>>(x);
    lstm_scan2<<<BB / 16, 512, scan_smem>>>(nullptr);      // writes g_out1

    // Layer 2
    prep_weights<<<1024, 256>>>(W_ih2, W_hh2, b_ih2, b_hh2, HH);
    gemm_gx_tf32<HH><<<ggrid, 256>>>(nullptr);
    lstm_scan2<<<BB / 16, 512, scan_smem>>>(out);           // writes final output
}

// round 6
// speedup vs baseline: 1.2260x; 1.1052x over previous
#include <cuda_runtime.h>
#include <math.h>
#include <stdint.h>

// Problem constants
#define BB 512
#define TT 168
#define II 64
#define HH 256
#define GG 1024   // 4*H
#define BT (BB*TT)
#define GXR 1032  // staged gx / gates smem row stride (floats) — 2-phase LDS.64

// ---------------------------------------------------------------------------
// Scratch (device globals: allocation-free rule)
// ---------------------------------------------------------------------------
__device__ float g_gx[(size_t)BT * GG];   // gate pre-activations, interleaved gate layout
__device__ float g_out1[(size_t)BT * HH]; // layer-1 hidden outputs
__device__ float g_WT[HH * GG];           // W_ih transposed+interleaved (GEMM B)
__device__ uint32_t g_WhhP[HH * GG];      // W_hh tf32, scan B-fragment layout (see prep)
__device__ float g_bias[GG];              // b_ih+b_hh, interleaved

// Interleaving: column n = j*4+q maps to raw gate row r = q*256 + j
// (q: 0=i, 1=f, 2=g, 3=o).

// ---------------------------------------------------------------------------
// tf32 / activation helpers
// ---------------------------------------------------------------------------
__device__ __forceinline__ uint32_t f2tf32(float x) {
    uint32_t r;
    asm("cvt.rna.tf32.f32 %0, %1;" : "=r"(r) : "f"(x));
    return r;
}

__device__ __forceinline__ void mma_tf32(float* c, const uint32_t* a, uint32_t b0, uint32_t b1) {
    asm volatile(
        "mma.sync.aligned.m16n8k8.row.col.f32.tf32.tf32.f32 "
        "{%0,%1,%2,%3}, {%4,%5,%6,%7}, {%8,%9}, {%0,%1,%2,%3};"
        : "+f"(c[0]), "+f"(c[1]), "+f"(c[2]), "+f"(c[3])
        : "r"(a[0]), "r"(a[1]), "r"(a[2]), "r"(a[3]), "r"(b0), "r"(b1));
}

__device__ __forceinline__ float sigmoid_fast(float x) {
    return __fdividef(1.f, 1.f + __expf(-x));   // EX2 + RCP path, ~2^-21 rel err
}
__device__ __forceinline__ float tanh_fast(float x) {
    float xc = fminf(fmaxf(x, -15.f), 15.f);
    float e = __expf(-2.f * xc);
    return __fdividef(1.f - e, 1.f + e);
}

// ---------------------------------------------------------------------------
// Weight prep: transpose + gate-interleave + bias combine + scan W permute.
// Scan W layout: warp w (of 16) owns n8-blocks nb in [w*8, w*8+8).
// One uint4 packs B-fragments (uint2 each) of two adjacent nb (pair p):
//   g_WhhP[ (((kblk*16 + w)*4 + p)*32 + lane)*4 + odd*2 + slot ]
// lane=(nin<<2)|(kin&3), slot=kin>>2, nb = w*8 + p*2 + odd.
// ---------------------------------------------------------------------------
__global__ void prep_weights(const float* __restrict__ W_ih,
                             const float* __restrict__ W_hh,
                             const float* __restrict__ b_ih,
                             const float* __restrict__ b_hh,
                             int K)
{
    int idx = blockIdx.x * 256 + threadIdx.x;  // 0 .. 256*1024-1
    int n = idx & (GG - 1);
    int k = idx >> 10;
    int j = n >> 2;
    int q = n & 3;
    int r = q * HH + j;
    if (k < K) g_WT[k * GG + n] = W_ih[r * K + k];

    {
        float wv = W_hh[r * HH + k];
        int nb = n >> 3, nin = n & 7;
        int w = nb >> 3, win = nb & 7, p = win >> 1, odd = win & 1;
        int kblk = k >> 3, kin = k & 7;
        int lane = (nin << 2) | (kin & 3);
        int slot = kin >> 2;
        size_t o = ((((size_t)(kblk * 16 + w) * 4 + p) * 32 + lane) << 2) + (odd << 1) + slot;
        g_WhhP[o] = f2tf32(wv);
    }
    if (k == 0) g_bias[n] = b_ih[r] + b_hh[r];
}

// ---------------------------------------------------------------------------
// Feed-forward GEMM (tensor cores, tf32): unchanged (validated R2-R5).
// ---------------------------------------------------------------------------
template <int K>
__global__ __launch_bounds__(256)
void gemm_gx_tf32(const float* __restrict__ X_in)
{
    const float* X = X_in ? X_in : (const float*)g_out1;
    constexpr int KT = K / 32;

    __shared__ uint32_t sA[2][4096];
    __shared__ uint32_t sB[2][2048];

    const int tid  = threadIdx.x;
    const int warp = tid >> 5;
    const int lane = tid & 31;
    const int m0 = blockIdx.x * 128;
    const int n0 = blockIdx.y * 64;
    const int wmb = (warp >> 1) * 2;
    const int wnb = (warp & 1) * 4;

    float acc[2][4][4];
#pragma unroll
    for (int i = 0; i < 2; i++)
#pragma unroll
        for (int j = 0; j < 4; j++)
#pragma unroll
            for (int q = 0; q < 4; q++) acc[i][j][q] = 0.f;

    float4 av[4];
    float4 bv[2];

    auto ldg_tile = [&](int kt) {
#pragma unroll
        for (int i = 0; i < 4; i++) {
            int v = tid + 256 * i;
            int row = v >> 3;
            int kc = (v & 7) * 4;
            av[i] = *(const float4*)(X + (size_t)(m0 + row) * K + kt * 32 + kc);
        }
#pragma unroll
        for (int i = 0; i < 2; i++) {
            int v = tid + 256 * i;
            int row = v >> 4;
            int nc = (v & 15) * 4;
            bv[i] = *(const float4*)(g_WT + (size_t)(kt * 32 + row) * GG + n0 + nc);
        }
    };

    auto sts_tile = [&](int buf) {
#pragma unroll
        for (int i = 0; i < 4; i++) {
            int v = tid + 256 * i;
            int row = v >> 3;
            int kc0 = (v & 7) * 4;
            int mblk = row >> 4, mr = row & 15;
            float f[4] = {av[i].x, av[i].y, av[i].z, av[i].w};
#pragma unroll
            for (int j = 0; j < 4; j++) {
                int kc = kc0 + j;
                int kblk = kc >> 3, kin = kc & 7;
                int t = ((mr & 7) << 2) | (kin & 3);
                int slot = ((kin >> 2) << 1) | (mr >> 3);
                sA[buf][(((kblk << 3) | mblk) << 7) + (t << 2) + slot] = f2tf32(f[j]);
            }
        }
#pragma unroll
        for (int i = 0; i < 2; i++) {
            int v = tid + 256 * i;
            int row = v >> 4;
            int nc0 = (v & 15) * 4;
            int kblk = row >> 3, kin = row & 7;
            float f[4] = {bv[i].x, bv[i].y, bv[i].z, bv[i].w};
#pragma unroll
            for (int j = 0; j < 4; j++) {
                int nc = nc0 + j;
                int nblk = nc >> 3, nin = nc & 7;
                int t = (nin << 2) | (kin & 3);
                int slot = kin >> 2;
                sB[buf][(((kblk << 3) | nblk) << 6) + (t << 1) + slot] = f2tf32(f[j]);
            }
        }
    };

    auto compute = [&](int buf) {
#pragma unroll
        for (int ks = 0; ks < 4; ks++) {
            uint32_t afr[2][4];
            uint32_t bfr[4][2];
#pragma unroll
            for (int mi = 0; mi < 2; mi++) {
                uint4 a = *(const uint4*)&sA[buf][(((ks << 3) | (wmb + mi)) << 7) + (lane << 2)];
                afr[mi][0] = a.x; afr[mi][1] = a.y; afr[mi][2] = a.z; afr[mi][3] = a.w;
            }
#pragma unroll
            for (int ni = 0; ni < 4; ni++) {
                uint2 b = *(const uint2*)&sB[buf][(((ks << 3) | (wnb + ni)) << 6) + (lane << 1)];
                bfr[ni][0] = b.x; bfr[ni][1] = b.y;
            }
#pragma unroll
            for (int mi = 0; mi < 2; mi++)
#pragma unroll
                for (int ni = 0; ni < 4; ni++)
                    mma_tf32(acc[mi][ni], afr[mi], bfr[ni][0], bfr[ni][1]);
        }
    };

    ldg_tile(0);
    sts_tile(0);
    __syncthreads();
#pragma unroll
    for (int kt = 0; kt < KT; kt++) {
        if (kt + 1 < KT) ldg_tile(kt + 1);
        compute(kt & 1);
        if (kt + 1 < KT) sts_tile((kt + 1) & 1);
        __syncthreads();
    }

    const int g = lane >> 2;
    const int cq = lane & 3;
#pragma unroll
    for (int ni = 0; ni < 4; ni++) {
        int gn = n0 + ((wnb + ni) << 3) + cq * 2;
        float bx = g_bias[gn];
        float by = g_bias[gn + 1];
#pragma unroll
        for (int mi = 0; mi < 2; mi++) {
            int gm = m0 + ((wmb + mi) << 4) + g;
            float2 r0 = make_float2(acc[mi][ni][0] + bx, acc[mi][ni][1] + by);
            float2 r1 = make_float2(acc[mi][ni][2] + bx, acc[mi][ni][3] + by);
            *(float2*)(g_gx + (size_t)gm * GG + gn) = r0;
            *(float2*)(g_gx + (size_t)(gm + 8) * GG + gn) = r1;
        }
    }
}

// ---------------------------------------------------------------------------
// Recurrent scan v3. 32 CTAs x MB=16 rows, 512 threads (16 warps).
// - gx[t+1] staged by cp.async into smem double buffer during step t
// - W streamed via ring-3 register prefetch (distance 2 > L2 latency)
// - fast EX2/RCP activations
// Two __syncthreads per step.
// ---------------------------------------------------------------------------
__global__ __launch_bounds__(512, 1)
void lstm_scan3(float* __restrict__ out_in)
{
    float* out = out_in ? out_in : (float*)g_out1;

    extern __shared__ float smem_f[];
    float* gx0   = smem_f;                  // [16][GXR]
    float* gx1   = gx0 + 16 * GXR;          // [16][GXR]
    float* gates = gx1 + 16 * GXR;          // [16][GXR]
    uint32_t* shA = (uint32_t*)(gates + 16 * GXR);  // [32 kblk][32 lane][4 slot]

    const int tid  = threadIdx.x;
    const int w    = tid >> 5;
    const int lane = tid & 31;
    const int g    = lane >> 2;
    const int cq   = lane & 3;
    const int b0   = blockIdx.x * 16;

    // update-phase constants: thread owns h column j, rows [rg*8, rg*8+8)
    const int j  = tid & 255;
    const int rg = tid >> 8;
    const int kblkU = j >> 3, kinU = j & 7;
    const int laneBase = kinU & 3;
    const int slotBase = (kinU >> 2) << 1;

    for (int i = tid; i < 4096; i += 512) shA[i] = 0u;
    float cst[8];
#pragma unroll
    for (int i = 0; i < 8; i++) cst[i] = 0.f;
    __syncthreads();

    const uint4* __restrict__ Wp = (const uint4*)g_WhhP;

    // cp.async staging: warp w stages batch row (b0+w), 4KB coalesced
    auto stage = [&](int t, float* buf) {
        const float* src = g_gx + ((size_t)(b0 + w) * TT + t) * GG;
        uint32_t dst = (uint32_t)__cvta_generic_to_shared(buf + w * GXR);
#pragma unroll
        for (int i = 0; i < 8; i++) {
            asm volatile("cp.async.cg.shared.global [%0], [%1], 16;"
                         :: "r"(dst + i * 512 + lane * 16),
                            "l"(src + i * 128 + lane * 4) : "memory");
        }
    };

    stage(0, gx0);
    asm volatile("cp.async.commit_group;" ::: "memory");

    for (int t = 0; t < TT; t++) {
        float* gxc = (t & 1) ? gx1 : gx0;
        float* gxn = (t & 1) ? gx0 : gx1;

        if (t + 1 < TT) {
            stage(t + 1, gxn);
            asm volatile("cp.async.commit_group;" ::: "memory");
            asm volatile("cp.async.wait_group 1;" ::: "memory");
        } else {
            asm volatile("cp.async.wait_group 0;" ::: "memory");
        }
        __syncthreads();   // gxc visible to all; shA(t-1) visible; gates free

        // ---- acc = gx fragments (from smem) ----
        float acc[8][4];
        {
            const float* rl = gxc + g * GXR + w * 64 + cq * 2;
            const float* rh = gxc + (g + 8) * GXR + w * 64 + cq * 2;
#pragma unroll
            for (int ni = 0; ni < 8; ni++) {
                float2 lo = *(const float2*)(rl + ni * 8);
                float2 hi = *(const float2*)(rh + ni * 8);
                acc[ni][0] = lo.x; acc[ni][1] = lo.y;
                acc[ni][2] = hi.x; acc[ni][3] = hi.y;
            }
        }

        // ---- mma over 32 kblks, W ring-3 register prefetch (distance 2) ----
        uint4 wb[3][4];
#pragma unroll
        for (int p = 0; p < 4; p++) wb[0][p] = Wp[(size_t)(((0 * 16 + w) * 4 + p) * 32) + lane];
#pragma unroll
        for (int p = 0; p < 4; p++) wb[1][p] = Wp[(size_t)(((1 * 16 + w) * 4 + p) * 32) + lane];

#pragma unroll
        for (int kb = 0; kb < 32; kb++) {
            if (kb + 2 < 32) {
#pragma unroll
                for (int p = 0; p < 4; p++)
                    wb[(kb + 2) % 3][p] = Wp[(size_t)((((kb + 2) * 16 + w) * 4 + p) * 32) + lane];
            }
            uint4 av = *(const uint4*)&shA[(kb * 32 + lane) * 4];
            uint32_t a[4] = {av.x, av.y, av.z, av.w};
            const uint4* wc = wb[kb % 3];
#pragma unroll
            for (int p = 0; p < 4; p++) {
                mma_tf32(acc[2 * p],     a, wc[p].x, wc[p].y);
                mma_tf32(acc[2 * p + 1], a, wc[p].z, wc[p].w);
            }
        }

        // ---- gates -> smem ----
#pragma unroll
        for (int ni = 0; ni < 8; ni++) {
            int n = w * 64 + ni * 8 + cq * 2;
            *(float2*)(gates + g * GXR + n) = make_float2(acc[ni][0], acc[ni][1]);
            *(float2*)(gates + (g + 8) * GXR + n) = make_float2(acc[ni][2], acc[ni][3]);
        }
        __syncthreads();

        // ---- elementwise LSTM update (fast activations) ----
#pragma unroll
        for (int i = 0; i < 8; i++) {
            int m = rg * 8 + i;
            float4 gv = *(const float4*)(gates + m * GXR + j * 4);
            float ig = sigmoid_fast(gv.x);
            float fg = sigmoid_fast(gv.y);
            float gg = tanh_fast(gv.z);
            float og = sigmoid_fast(gv.w);
            float cn = fg * cst[i] + ig * gg;
            cst[i] = cn;
            float h = og * tanh_fast(cn);
            out[((size_t)(b0 + m) * TT + t) * HH + j] = h;
            int laneA = ((m & 7) << 2) | laneBase;
            int slot  = slotBase | (m >> 3);
            shA[(kblkU * 32 + laneA) * 4 + slot] = f2tf32(h);
        }
        // no sync here: next iteration's post-wait __syncthreads covers
        // shA(write)->mma(read) and gates(read)->gates(write) hazards.
    }
}

// ---------------------------------------------------------------------------
// Launch
// ---------------------------------------------------------------------------
extern "C" void kernel_launch(void* const* d_in, const int* in_sizes, int n_in,
                              void* d_out, int out_size)
{
    const float* x     = (const float*)d_in[0];
    const float* W_ih1 = (const float*)d_in[1];
    const float* W_hh1 = (const float*)d_in[2];
    const float* b_ih1 = (const float*)d_in[3];
    const float* b_hh1 = (const float*)d_in[4];
    const float* W_ih2 = (const float*)d_in[5];
    const float* W_hh2 = (const float*)d_in[6];
    const float* b_ih2 = (const float*)d_in[7];
    const float* b_hh2 = (const float*)d_in[8];
    float* out = (float*)d_out;

    const int scan_smem = 3 * 16 * GXR * 4 + 4096 * 4;   // 214,528 B
    cudaFuncSetAttribute(lstm_scan3,
                         cudaFuncAttributeMaxDynamicSharedMemorySize, scan_smem);

    dim3 ggrid(BT / 128, GG / 64);  // 672 x 16

    // Layer 1
    prep_weights<<<1024, 256>>>(W_ih1, W_hh1, b_ih1, b_hh1, II);
    gemm_gx_tf32<II><<<ggrid, 256>>>(x);
    lstm_scan3<<<BB / 16, 512, scan_smem>>>(nullptr);      // writes g_out1

    // Layer 2
    prep_weights<<<1024, 256>>>(W_ih2, W_hh2, b_ih2, b_hh2, HH);
    gemm_gx_tf32<HH><<<ggrid, 256>>>(nullptr);
    lstm_scan3<<<BB / 16, 512, scan_smem>>>(out);           // writes final output
}

// round 7
// speedup vs baseline: 1.6483x; 1.3444x over previous
#include <cuda_runtime.h>
#include <cuda_fp16.h>
#include <math.h>
#include <stdint.h>

// Problem constants
#define BB 512
#define TT 168
#define II 64
#define HH 256
#define GG 1024   // 4*H
#define BT (BB*TT)
#define GXR 1032  // staged gx / gates smem row stride (floats)

// ---------------------------------------------------------------------------
// Scratch (device globals: allocation-free rule)
// ---------------------------------------------------------------------------
__device__ float g_gx[(size_t)BT * GG];   // gate pre-activations, interleaved gate layout
__device__ float g_out1[(size_t)BT * HH]; // layer-1 hidden outputs
__device__ float g_WT[HH * GG];           // W_ih transposed+interleaved (GEMM B)
__device__ __half g_WhhPh[HH * GG];       // W_hh fp16, scan B-fragment layout (see prep)
__device__ float g_bias[GG];              // b_ih+b_hh, interleaved

// Interleaving: column n = j*4+q maps to raw gate row r = q*256 + j
// (q: 0=i, 1=f, 2=g, 3=o).

// ---------------------------------------------------------------------------
// tf32 / fp16 mma / activation helpers
// ---------------------------------------------------------------------------
__device__ __forceinline__ uint32_t f2tf32(float x) {
    uint32_t r;
    asm("cvt.rna.tf32.f32 %0, %1;" : "=r"(r) : "f"(x));
    return r;
}

__device__ __forceinline__ void mma_tf32(float* c, const uint32_t* a, uint32_t b0, uint32_t b1) {
    asm volatile(
        "mma.sync.aligned.m16n8k8.row.col.f32.tf32.tf32.f32 "
        "{%0,%1,%2,%3}, {%4,%5,%6,%7}, {%8,%9}, {%0,%1,%2,%3};"
        : "+f"(c[0]), "+f"(c[1]), "+f"(c[2]), "+f"(c[3])
        : "r"(a[0]), "r"(a[1]), "r"(a[2]), "r"(a[3]), "r"(b0), "r"(b1));
}

// m16n8k16 fp16 inputs, fp32 accumulate
__device__ __forceinline__ void mma_f16(float* c, const uint32_t* a, uint32_t b0, uint32_t b1) {
    asm volatile(
        "mma.sync.aligned.m16n8k16.row.col.f32.f16.f16.f32 "
        "{%0,%1,%2,%3}, {%4,%5,%6,%7}, {%8,%9}, {%0,%1,%2,%3};"
        : "+f"(c[0]), "+f"(c[1]), "+f"(c[2]), "+f"(c[3])
        : "r"(a[0]), "r"(a[1]), "r"(a[2]), "r"(a[3]), "r"(b0), "r"(b1));
}

__device__ __forceinline__ float sigmoid_fast(float x) {
    return __fdividef(1.f, 1.f + __expf(-x));
}
__device__ __forceinline__ float tanh_fast(float x) {
    float xc = fminf(fmaxf(x, -15.f), 15.f);
    float e = __expf(-2.f * xc);
    return __fdividef(1.f - e, 1.f + e);
}

// ---------------------------------------------------------------------------
// Weight prep: transpose + gate-interleave + bias combine + scan W permute.
// Scan W fp16 layout (m16n8k16 B fragments): warp w of 16 owns n8-blocks
// nb in [w*8, w*8+8); pair p = 0..3, odd = nb&1. One uint4 = B-frags (uint2)
// of nb = w*8+p*2 and w*8+p*2+1 for one kblk (K=16):
//   word index = (((kblk*16 + w)*4 + p)*32 + lane)*4 + (odd*2 + ridx)
//   lane = (nin<<2) | ((kin&7)>>1), ridx = kin>>3, half = kin&1
// ---------------------------------------------------------------------------
__global__ void prep_weights(const float* __restrict__ W_ih,
                             const float* __restrict__ W_hh,
                             const float* __restrict__ b_ih,
                             const float* __restrict__ b_hh,
                             int K)
{
    int idx = blockIdx.x * 256 + threadIdx.x;  // 0 .. 256*1024-1
    int n = idx & (GG - 1);
    int k = idx >> 10;
    int j = n >> 2;
    int q = n & 3;
    int r = q * HH + j;
    if (k < K) g_WT[k * GG + n] = W_ih[r * K + k];

    {
        float wv = W_hh[r * HH + k];
        int nb = n >> 3, nin = n & 7;
        int w = nb >> 3, win = nb & 7, p = win >> 1, odd = win & 1;
        int kblk = k >> 4, kin = k & 15;
        int lane = (nin << 2) | ((kin & 7) >> 1);
        int ridx = kin >> 3;
        int hf   = kin & 1;
        size_t o = (((((size_t)(kblk * 16 + w) * 4 + p) * 32 + lane) * 4)
                    + (odd * 2 + ridx)) * 2 + hf;
        g_WhhPh[o] = __float2half_rn(wv);
    }
    if (k == 0) g_bias[n] = b_ih[r] + b_hh[r];
}

// ---------------------------------------------------------------------------
// Feed-forward GEMM (tensor cores, tf32): unchanged (validated R2-R6).
// ---------------------------------------------------------------------------
template <int K>
__global__ __launch_bounds__(256)
void gemm_gx_tf32(const float* __restrict__ X_in)
{
    const float* X = X_in ? X_in : (const float*)g_out1;
    constexpr int KT = K / 32;

    __shared__ uint32_t sA[2][4096];
    __shared__ uint32_t sB[2][2048];

    const int tid  = threadIdx.x;
    const int warp = tid >> 5;
    const int lane = tid & 31;
    const int m0 = blockIdx.x * 128;
    const int n0 = blockIdx.y * 64;
    const int wmb = (warp >> 1) * 2;
    const int wnb = (warp & 1) * 4;

    float acc[2][4][4];
#pragma unroll
    for (int i = 0; i < 2; i++)
#pragma unroll
        for (int j = 0; j < 4; j++)
#pragma unroll
            for (int q = 0; q < 4; q++) acc[i][j][q] = 0.f;

    float4 av[4];
    float4 bv[2];

    auto ldg_tile = [&](int kt) {
#pragma unroll
        for (int i = 0; i < 4; i++) {
            int v = tid + 256 * i;
            int row = v >> 3;
            int kc = (v & 7) * 4;
            av[i] = *(const float4*)(X + (size_t)(m0 + row) * K + kt * 32 + kc);
        }
#pragma unroll
        for (int i = 0; i < 2; i++) {
            int v = tid + 256 * i;
            int row = v >> 4;
            int nc = (v & 15) * 4;
            bv[i] = *(const float4*)(g_WT + (size_t)(kt * 32 + row) * GG + n0 + nc);
        }
    };

    auto sts_tile = [&](int buf) {
#pragma unroll
        for (int i = 0; i < 4; i++) {
            int v = tid + 256 * i;
            int row = v >> 3;
            int kc0 = (v & 7) * 4;
            int mblk = row >> 4, mr = row & 15;
            float f[4] = {av[i].x, av[i].y, av[i].z, av[i].w};
#pragma unroll
            for (int j = 0; j < 4; j++) {
                int kc = kc0 + j;
                int kblk = kc >> 3, kin = kc & 7;
                int t = ((mr & 7) << 2) | (kin & 3);
                int slot = ((kin >> 2) << 1) | (mr >> 3);
                sA[buf][(((kblk << 3) | mblk) << 7) + (t << 2) + slot] = f2tf32(f[j]);
            }
        }
#pragma unroll
        for (int i = 0; i < 2; i++) {
            int v = tid + 256 * i;
            int row = v >> 4;
            int nc0 = (v & 15) * 4;
            int kblk = row >> 3, kin = row & 7;
            float f[4] = {bv[i].x, bv[i].y, bv[i].z, bv[i].w};
#pragma unroll
            for (int j = 0; j < 4; j++) {
                int nc = nc0 + j;
                int nblk = nc >> 3, nin = nc & 7;
                int t = (nin << 2) | (kin & 3);
                int slot = kin >> 2;
                sB[buf][(((kblk << 3) | nblk) << 6) + (t << 1) + slot] = f2tf32(f[j]);
            }
        }
    };

    auto compute = [&](int buf) {
#pragma unroll
        for (int ks = 0; ks < 4; ks++) {
            uint32_t afr[2][4];
            uint32_t bfr[4][2];
#pragma unroll
            for (int mi = 0; mi < 2; mi++) {
                uint4 a = *(const uint4*)&sA[buf][(((ks << 3) | (wmb + mi)) << 7) + (lane << 2)];
                afr[mi][0] = a.x; afr[mi][1] = a.y; afr[mi][2] = a.z; afr[mi][3] = a.w;
            }
#pragma unroll
            for (int ni = 0; ni < 4; ni++) {
                uint2 b = *(const uint2*)&sB[buf][(((ks << 3) | (wnb + ni)) << 6) + (lane << 1)];
                bfr[ni][0] = b.x; bfr[ni][1] = b.y;
            }
#pragma unroll
            for (int mi = 0; mi < 2; mi++)
#pragma unroll
                for (int ni = 0; ni < 4; ni++)
                    mma_tf32(acc[mi][ni], afr[mi], bfr[ni][0], bfr[ni][1]);
        }
    };

    ldg_tile(0);
    sts_tile(0);
    __syncthreads();
#pragma unroll
    for (int kt = 0; kt < KT; kt++) {
        if (kt + 1 < KT) ldg_tile(kt + 1);
        compute(kt & 1);
        if (kt + 1 < KT) sts_tile((kt + 1) & 1);
        __syncthreads();
    }

    const int g = lane >> 2;
    const int cq = lane & 3;
#pragma unroll
    for (int ni = 0; ni < 4; ni++) {
        int gn = n0 + ((wnb + ni) << 3) + cq * 2;
        float bx = g_bias[gn];
        float by = g_bias[gn + 1];
#pragma unroll
        for (int mi = 0; mi < 2; mi++) {
            int gm = m0 + ((wmb + mi) << 4) + g;
            float2 r0 = make_float2(acc[mi][ni][0] + bx, acc[mi][ni][1] + by);
            float2 r1 = make_float2(acc[mi][ni][2] + bx, acc[mi][ni][3] + by);
            *(float2*)(g_gx + (size_t)gm * GG + gn) = r0;
            *(float2*)(g_gx + (size_t)(gm + 8) * GG + gn) = r1;
        }
    }
}

// ---------------------------------------------------------------------------
// Recurrent scan v4 (fp16 HMMA m16n8k16). 32 CTAs x MB=16 rows, 512 threads.
// W_hh fp16 -> 512KB streamed per step (half of v3); h kept fp16 in shA.
// gx[t+1] cp.async double-buffered; ring-3 W register prefetch; fast
// activations; fp32 accumulation throughout. Two __syncthreads per step.
// ---------------------------------------------------------------------------
__global__ __launch_bounds__(512, 1)
void lstm_scan4(float* __restrict__ out_in)
{
    float* out = out_in ? out_in : (float*)g_out1;

    extern __shared__ float smem_f[];
    float* gx0   = smem_f;                  // [16][GXR]
    float* gx1   = gx0 + 16 * GXR;          // [16][GXR]
    float* gates = gx1 + 16 * GXR;          // [16][GXR]
    uint32_t* shA = (uint32_t*)(gates + 16 * GXR);  // [16 kblk][32 lane][4 words] fp16 pairs
    __half* shA_h = (__half*)shA;

    const int tid  = threadIdx.x;
    const int w    = tid >> 5;
    const int lane = tid & 31;
    const int g    = lane >> 2;
    const int cq   = lane & 3;
    const int b0   = blockIdx.x * 16;

    // update-phase constants: thread owns h column j, rows [rg*8, rg*8+8)
    const int j  = tid & 255;
    const int rg = tid >> 8;
    const int kblkU = j >> 4, kinU = j & 15;
    const int cqU   = (kinU & 7) >> 1;
    const int hfU   = kinU & 1;
    const int ridxU = kinU >> 3;

    for (int i = tid; i < 2048; i += 512) shA[i] = 0u;
    float cst[8];
#pragma unroll
    for (int i = 0; i < 8; i++) cst[i] = 0.f;
    __syncthreads();

    const uint4* __restrict__ Wp = (const uint4*)g_WhhPh;

    // cp.async staging: warp w stages batch row (b0+w), 4KB coalesced
    auto stage = [&](int t, float* buf) {
        const float* src = g_gx + ((size_t)(b0 + w) * TT + t) * GG;
        uint32_t dst = (uint32_t)__cvta_generic_to_shared(buf + w * GXR);
#pragma unroll
        for (int i = 0; i < 8; i++) {
            asm volatile("cp.async.cg.shared.global [%0], [%1], 16;"
                         :: "r"(dst + i * 512 + lane * 16),
                            "l"(src + i * 128 + lane * 4) : "memory");
        }
    };

    stage(0, gx0);
    asm volatile("cp.async.commit_group;" ::: "memory");

    for (int t = 0; t < TT; t++) {
        float* gxc = (t & 1) ? gx1 : gx0;
        float* gxn = (t & 1) ? gx0 : gx1;

        if (t + 1 < TT) {
            stage(t + 1, gxn);
            asm volatile("cp.async.commit_group;" ::: "memory");
            asm volatile("cp.async.wait_group 1;" ::: "memory");
        } else {
            asm volatile("cp.async.wait_group 0;" ::: "memory");
        }
        __syncthreads();   // gxc visible; shA(t-1) visible; gates free

        // ---- acc = gx fragments (from smem) ----
        float acc[8][4];
        {
            const float* rl = gxc + g * GXR + w * 64 + cq * 2;
            const float* rh = gxc + (g + 8) * GXR + w * 64 + cq * 2;
#pragma unroll
            for (int ni = 0; ni < 8; ni++) {
                float2 lo = *(const float2*)(rl + ni * 8);
                float2 hi = *(const float2*)(rh + ni * 8);
                acc[ni][0] = lo.x; acc[ni][1] = lo.y;
                acc[ni][2] = hi.x; acc[ni][3] = hi.y;
            }
        }

        // ---- mma over 16 kblks (K=16 each), W ring-3 register prefetch ----
        uint4 wb[3][4];
#pragma unroll
        for (int p = 0; p < 4; p++) wb[0][p] = Wp[(size_t)(((0 * 16 + w) * 4 + p) * 32) + lane];
#pragma unroll
        for (int p = 0; p < 4; p++) wb[1][p] = Wp[(size_t)(((1 * 16 + w) * 4 + p) * 32) + lane];

#pragma unroll
        for (int kb = 0; kb < 16; kb++) {
            if (kb + 2 < 16) {
#pragma unroll
                for (int p = 0; p < 4; p++)
                    wb[(kb + 2) % 3][p] = Wp[(size_t)((((kb + 2) * 16 + w) * 4 + p) * 32) + lane];
            }
            uint4 av = *(const uint4*)&shA[(kb * 32 + lane) * 4];
            uint32_t a[4] = {av.x, av.y, av.z, av.w};
            const uint4* wc = wb[kb % 3];
#pragma unroll
            for (int p = 0; p < 4; p++) {
                mma_f16(acc[2 * p],     a, wc[p].x, wc[p].y);
                mma_f16(acc[2 * p + 1], a, wc[p].z, wc[p].w);
            }
        }

        // ---- gates -> smem ----
#pragma unroll
        for (int ni = 0; ni < 8; ni++) {
            int n = w * 64 + ni * 8 + cq * 2;
            *(float2*)(gates + g * GXR + n) = make_float2(acc[ni][0], acc[ni][1]);
            *(float2*)(gates + (g + 8) * GXR + n) = make_float2(acc[ni][2], acc[ni][3]);
        }
        __syncthreads();

        // ---- elementwise LSTM update (fast activations), h -> fp16 shA ----
#pragma unroll
        for (int i = 0; i < 8; i++) {
            int m = rg * 8 + i;
            float4 gv = *(const float4*)(gates + m * GXR + j * 4);
            float ig = sigmoid_fast(gv.x);
            float fg = sigmoid_fast(gv.y);
            float gg = tanh_fast(gv.z);
            float og = sigmoid_fast(gv.w);
            float cn = fg * cst[i] + ig * gg;
            cst[i] = cn;
            float h = og * tanh_fast(cn);
            out[((size_t)(b0 + m) * TT + t) * HH + j] = h;
            // fp16 A-fragment store: word = (ridx<<1)|(m>>3), lane=((m&7)<<2)|cqU
            int laneA = ((m & 7) << 2) | cqU;
            int word  = (ridxU << 1) | (m >> 3);
            shA_h[(((kblkU * 32 + laneA) << 2) + word) * 2 + hfU] = __float2half_rn(h);
        }
        // no sync: next iteration's post-wait __syncthreads covers hazards.
    }
}

// ---------------------------------------------------------------------------
// Launch
// ---------------------------------------------------------------------------
extern "C" void kernel_launch(void* const* d_in, const int* in_sizes, int n_in,
                              void* d_out, int out_size)
{
    const float* x     = (const float*)d_in[0];
    const float* W_ih1 = (const float*)d_in[1];
    const float* W_hh1 = (const float*)d_in[2];
    const float* b_ih1 = (const float*)d_in[3];
    const float* b_hh1 = (const float*)d_in[4];
    const float* W_ih2 = (const float*)d_in[5];
    const float* W_hh2 = (const float*)d_in[6];
    const float* b_ih2 = (const float*)d_in[7];
    const float* b_hh2 = (const float*)d_in[8];
    float* out = (float*)d_out;

    const int scan_smem = 3 * 16 * GXR * 4 + 2048 * 4;   // 206,336 B
    cudaFuncSetAttribute(lstm_scan4,
                         cudaFuncAttributeMaxDynamicSharedMemorySize, scan_smem);

    dim3 ggrid(BT / 128, GG / 64);  // 672 x 16

    // Layer 1
    prep_weights<<<1024, 256>>>(W_ih1, W_hh1, b_ih1, b_hh1, II);
    gemm_gx_tf32<II><<<ggrid, 256>>>(x);
    lstm_scan4<<<BB / 16, 512, scan_smem>>>(nullptr);      // writes g_out1

    // Layer 2
    prep_weights<<<1024, 256>>>(W_ih2, W_hh2, b_ih2, b_hh2, HH);
    gemm_gx_tf32<HH><<<ggrid, 256>>>(nullptr);
    lstm_scan4<<<BB / 16, 512, scan_smem>>>(out);           // writes final output
}